// round 3
// baseline (speedup 1.0000x reference)
#include <cuda_runtime.h>

#define NN 50000
#define EE 800000
#define DD 128
#define NH 8
#define TE 64
#define AS 164   // padded row stride for the activation tile (164%32==4 -> mild conflicts only)

// ---------------- scratch (static __device__ -- no allocations allowed) ----------------
__device__ float    g_msg[(size_t)EE * DD];   // 409.6 MB
__device__ float    g_a[(size_t)EE * NH];     // 25.6 MB
__device__ float    g_agg[(size_t)NN * DD];   // 25.6 MB
__device__ unsigned g_maxbits[NH];
__device__ float    g_sum[NH];

__device__ __forceinline__ float siluf(float x) { return x / (1.f + __expf(-x)); }
__device__ __forceinline__ unsigned encf(float x) {
    unsigned u = __float_as_uint(x);
    return (u & 0x80000000u) ? ~u : (u | 0x80000000u);
}
__device__ __forceinline__ float decf(unsigned u) {
    return __uint_as_float((u & 0x80000000u) ? (u ^ 0x80000000u) : ~u);
}

// ---------------- register-tiled GEMM: C[64 x 128] = sA[64 x K] @ W[K x 128] ----------
// 256 threads; thread(tx,ty) owns rows ty*8..ty*8+7, cols tx*4..tx*4+3.
// Weights streamed gmem -> shared in K-chunks of 32. No trailing sync (callers sync).
template<int K, bool CLEAR>
__device__ __forceinline__ void tile_gemm(const float* __restrict__ W,
        const float* sA, int lda, float (&acc)[8][4], float* sW,
        int tx, int ty, int tid)
{
    if (CLEAR) {
#pragma unroll
        for (int i = 0; i < 8; i++)
#pragma unroll
            for (int j = 0; j < 4; j++) acc[i][j] = 0.f;
    }
    const int r0 = ty * 8;
    constexpr int CH = (K < 32) ? K : 32;
    for (int kc = 0; kc < K; kc += CH) {
        __syncthreads();
        for (int idx = tid; idx < CH * 32; idx += 256) {
            int r = idx >> 5, c = (idx & 31) << 2;
            *(float4*)(sW + r * 128 + c) = *(const float4*)(W + (size_t)(kc + r) * 128 + c);
        }
        __syncthreads();
#pragma unroll 8
        for (int k = 0; k < CH; k++) {
            float4 w4 = *(const float4*)(sW + k * 128 + (tx << 2));
            float a[8];
#pragma unroll
            for (int i = 0; i < 8; i++) a[i] = sA[(r0 + i) * lda + kc + k];
#pragma unroll
            for (int i = 0; i < 8; i++) {
                acc[i][0] += a[i] * w4.x;
                acc[i][1] += a[i] * w4.y;
                acc[i][2] += a[i] * w4.z;
                acc[i][3] += a[i] * w4.w;
            }
        }
    }
}

__device__ __forceinline__ void epilogue_silu(float (&acc)[8][4], const float* sb,
                                              float* s_A, int r0, int tx)
{
#pragma unroll
    for (int i = 0; i < 8; i++) {
        float4 v;
        v.x = siluf(acc[i][0] + sb[tx * 4 + 0]);
        v.y = siluf(acc[i][1] + sb[tx * 4 + 1]);
        v.z = siluf(acc[i][2] + sb[tx * 4 + 2]);
        v.w = siluf(acc[i][3] + sb[tx * 4 + 3]);
        *(float4*)(s_A + (r0 + i) * AS + tx * 4) = v;
    }
}

// ---------------- K0: init scratch ----------------
__global__ void k_init()
{
    int i = blockIdx.x * blockDim.x + threadIdx.x;
    int stride = gridDim.x * blockDim.x;
    for (int j = i; j < NN * DD; j += stride) g_agg[j] = 0.f;
    if (i < NH) { g_maxbits[i] = 0u; g_sum[i] = 0.f; }
}

// ---------------- K1: fused per-edge kernel ----------------
// Per 64-edge tile: attention MLP (logits -> g_a + global max), message MLP (-> g_msg).
__global__ void __launch_bounds__(256, 2)
k_edge(const float* __restrict__ nf, const float* __restrict__ edge_attr,
       const float* __restrict__ edge_sh,
       const float* __restrict__ W_node,
       const float* __restrict__ fc1, const float* __restrict__ b1,
       const float* __restrict__ fc2, const float* __restrict__ b2,
       const float* __restrict__ fc3, const float* __restrict__ b3,
       const float* __restrict__ W_sh,
       const float* __restrict__ aW1, const float* __restrict__ ab1,
       const float* __restrict__ aW2, const float* __restrict__ ab2,
       const float* __restrict__ aW3, const float* __restrict__ ab3,
       const int* __restrict__ edge_index)
{
    extern __shared__ float smem[];
    float*    s_A    = smem;                       // TE*AS   = 10496 f
    float*    s_W    = s_A  + TE * AS;             // 32*128  = 4096 f
    float*    s_ea   = s_W  + 32 * 128;            // TE*32   = 2048 f
    float*    s_sh   = s_ea + TE * 32;             // TE*16   = 1024 f
    float*    s_bias = s_sh + TE * 16;             // 5*128   = 640 f
    int*      s_src  = (int*)(s_bias + 640);       // TE
    int*      s_dst  = s_src + TE;                 // TE
    unsigned* s_maxb = (unsigned*)(s_dst + TE);    // NH

    const int tid = threadIdx.x, tx = tid & 31, ty = tid >> 5;
    const int e0 = blockIdx.x * TE;
    const int r0 = ty * 8;

    if (tid < TE) {
        s_src[tid] = edge_index[e0 + tid];
        s_dst[tid] = edge_index[EE + e0 + tid];
    }
    if (tid < NH) s_maxb[tid] = 0u;
    if (tid < 128) {
        s_bias[tid]       = b1[tid];
        s_bias[128 + tid] = b2[tid];
        s_bias[256 + tid] = b3[tid];
        s_bias[384 + tid] = ab1[tid];
        s_bias[512 + tid] = ab2[tid];
    }
    for (int idx = tid; idx < TE * 8; idx += 256) {     // edge_attr [TE][32]
        int r = idx >> 3, c = (idx & 7) << 2;
        *(float4*)(s_ea + r * 32 + c) = *(const float4*)(edge_attr + (size_t)(e0 + r) * 32 + c);
    }
    for (int idx = tid; idx < TE * 4; idx += 256) {     // edge_sh [TE][16]
        int r = idx >> 2, c = (idx & 3) << 2;
        *(float4*)(s_sh + r * 16 + c) = *(const float4*)(edge_sh + (size_t)(e0 + r) * 16 + c);
    }
    __syncthreads();

    // ---- Phase A: attention branch ----
    // alpha_in in s_A: [ x_src[:64] | x_dst[:64] | edge_attr ]
#pragma unroll
    for (int i = 0; i < 8; i++) {
        int r = r0 + i;
        int s = s_src[r], d = s_dst[r];
        *(float2*)(s_A + r * AS + tx * 2)      = *(const float2*)(nf + (size_t)s * DD + tx * 2);
        *(float2*)(s_A + r * AS + 64 + tx * 2) = *(const float2*)(nf + (size_t)d * DD + tx * 2);
    }
    for (int idx = tid; idx < TE * 8; idx += 256) {
        int r = idx >> 3, c = (idx & 7) << 2;
        *(float4*)(s_A + r * AS + 128 + c) = *(const float4*)(s_ea + r * 32 + c);
    }

    float acc[8][4];
    tile_gemm<160, true>(aW1, s_A, AS, acc, s_W, tx, ty, tid);
    __syncthreads();
    epilogue_silu(acc, s_bias + 384, s_A, r0, tx);

    tile_gemm<128, true>(aW2, s_A, AS, acc, s_W, tx, ty, tid);
    __syncthreads();
    epilogue_silu(acc, s_bias + 512, s_A, r0, tx);
    __syncthreads();

    // small layer: a[TE][8] = t2 @ aW3 + ab3 ; also per-head block max
    *(float4*)(s_W + tid * 4) = *(const float4*)(aW3 + tid * 4);   // 1024 floats, 1 f4/thread
    __syncthreads();
    if (tid < TE) {
        float av[NH];
#pragma unroll
        for (int h = 0; h < NH; h++) av[h] = ab3[h];
        for (int k = 0; k < 128; k++) {
            float x = s_A[tid * AS + k];
#pragma unroll
            for (int h = 0; h < NH; h++) av[h] += x * s_W[k * 8 + h];
        }
        float4* gp = (float4*)(g_a + (size_t)(e0 + tid) * NH);
        gp[0] = make_float4(av[0], av[1], av[2], av[3]);
        gp[1] = make_float4(av[4], av[5], av[6], av[7]);
#pragma unroll
        for (int h = 0; h < NH; h++) atomicMax(&s_maxb[h], encf(av[h]));
    }
    __syncthreads();
    if (tid < NH) atomicMax(&g_maxbits[tid], s_maxb[tid]);

    // ---- Phase B: message branch ----
    tile_gemm<32, true>(fc1, s_ea, 32, acc, s_W, tx, ty, tid);
    __syncthreads();
    epilogue_silu(acc, s_bias + 0, s_A, r0, tx);

    tile_gemm<128, true>(fc2, s_A, AS, acc, s_W, tx, ty, tid);
    __syncthreads();
    epilogue_silu(acc, s_bias + 128, s_A, r0, tx);

    tile_gemm<128, true>(fc3, s_A, AS, acc, s_W, tx, ty, tid);
    float scale[8][4];
#pragma unroll
    for (int i = 0; i < 8; i++)
#pragma unroll
        for (int j = 0; j < 4; j++) scale[i][j] = acc[i][j] + s_bias[256 + tx * 4 + j];
    __syncthreads();

    // gather full x_src into s_A (rows are warp-private)
#pragma unroll
    for (int i = 0; i < 8; i++) {
        int r = r0 + i;
        int s = s_src[r];
        *(float4*)(s_A + r * AS + tx * 4) = *(const float4*)(nf + (size_t)s * DD + tx * 4);
    }
    tile_gemm<128, true>(W_node, s_A, AS, acc, s_W, tx, ty, tid);
#pragma unroll
    for (int i = 0; i < 8; i++)
#pragma unroll
        for (int j = 0; j < 4; j++) acc[i][j] *= scale[i][j];
    tile_gemm<16, false>(W_sh, s_sh, 16, acc, s_W, tx, ty, tid);   // accumulate sh projection

#pragma unroll
    for (int i = 0; i < 8; i++) {
        int r = r0 + i;
        float4 m;
        m.x = siluf(acc[i][0]);
        m.y = siluf(acc[i][1]);
        m.z = siluf(acc[i][2]);
        m.w = siluf(acc[i][3]);
        *(float4*)(g_msg + (size_t)(e0 + r) * DD + tx * 4) = m;
    }
}

// ---------------- K2: per-head sum of exp(a - max) ----------------
__global__ void k_sumexp()
{
    __shared__ float s_sum[NH];
    if (threadIdx.x < NH) s_sum[threadIdx.x] = 0.f;
    __syncthreads();
    float mx[NH];
#pragma unroll
    for (int h = 0; h < NH; h++) mx[h] = decf(g_maxbits[h]);
    float loc[NH];
#pragma unroll
    for (int h = 0; h < NH; h++) loc[h] = 0.f;
    for (int e = blockIdx.x * blockDim.x + threadIdx.x; e < EE; e += gridDim.x * blockDim.x) {
        const float4 a0 = *(const float4*)(g_a + (size_t)e * NH);
        const float4 a1 = *(const float4*)(g_a + (size_t)e * NH + 4);
        loc[0] += __expf(a0.x - mx[0]); loc[1] += __expf(a0.y - mx[1]);
        loc[2] += __expf(a0.z - mx[2]); loc[3] += __expf(a0.w - mx[3]);
        loc[4] += __expf(a1.x - mx[4]); loc[5] += __expf(a1.y - mx[5]);
        loc[6] += __expf(a1.z - mx[6]); loc[7] += __expf(a1.w - mx[7]);
    }
#pragma unroll
    for (int h = 0; h < NH; h++) atomicAdd(&s_sum[h], loc[h]);
    __syncthreads();
    if (threadIdx.x < NH) atomicAdd(&g_sum[threadIdx.x], s_sum[threadIdx.x]);
}

// ---------------- K3: scatter msg * alpha_mean into g_agg[dst] ----------------
__global__ void k_scatter(const int* __restrict__ edge_index)
{
    const int lane  = threadIdx.x & 31;
    const int warp  = blockIdx.x * (blockDim.x >> 5) + (threadIdx.x >> 5);
    const int nwarp = gridDim.x * (blockDim.x >> 5);
    float mxh = 0.f, ish = 0.f;
    if (lane < NH) {
        mxh = decf(g_maxbits[lane]);
        ish = 1.f / g_sum[lane];
    }
    for (int e = warp; e < EE; e += nwarp) {
        float v = 0.f;
        if (lane < NH) v = __expf(g_a[(size_t)e * NH + lane] - mxh) * ish;
#pragma unroll
        for (int o = 4; o > 0; o >>= 1) v += __shfl_down_sync(0xffffffffu, v, o);
        float w = __shfl_sync(0xffffffffu, v, 0) * 0.125f;
        int d = edge_index[EE + e];
        const float4 m = *(const float4*)(g_msg + (size_t)e * DD + lane * 4);
        float* p = g_agg + (size_t)d * DD + lane * 4;
        atomicAdd(p + 0, m.x * w);
        atomicAdd(p + 1, m.y * w);
        atomicAdd(p + 2, m.z * w);
        atomicAdd(p + 3, m.w * w);
    }
}

// ---------------- K4: out = LN(nf + agg @ W_out) ----------------
__global__ void k_node(const float* __restrict__ nf, const float* __restrict__ W_out,
                       float* __restrict__ out)
{
    extern __shared__ float smem[];
    float* sW    = smem;              // 128*128
    float* s_row = sW + 128 * 128;    // 8*128
    const int tid = threadIdx.x, tx = tid & 31, w = tid >> 5;
    for (int idx = tid; idx < 128 * 32; idx += 256) {
        int r = idx >> 5, c = (idx & 31) << 2;
        *(float4*)(sW + r * 128 + c) = *(const float4*)(W_out + (size_t)r * 128 + c);
    }
    __syncthreads();
    for (int n = blockIdx.x * 8 + w; n < NN; n += gridDim.x * 8) {
        float4 av = *(const float4*)(g_agg + (size_t)n * DD + tx * 4);
        __syncwarp();
        *(float4*)(s_row + w * 128 + tx * 4) = av;
        __syncwarp();
        float a0 = 0.f, a1 = 0.f, a2 = 0.f, a3 = 0.f;
#pragma unroll 8
        for (int k = 0; k < 128; k++) {
            float a = s_row[w * 128 + k];
            const float4 wv = *(const float4*)(sW + k * 128 + tx * 4);
            a0 += a * wv.x; a1 += a * wv.y; a2 += a * wv.z; a3 += a * wv.w;
        }
        const float4 x = *(const float4*)(nf + (size_t)n * DD + tx * 4);
        float v0 = x.x + a0, v1 = x.y + a1, v2 = x.z + a2, v3 = x.w + a3;
        float s = v0 + v1 + v2 + v3;
#pragma unroll
        for (int o = 16; o > 0; o >>= 1) s += __shfl_xor_sync(0xffffffffu, s, o);
        float mu = s * (1.f / 128.f);
        float d0 = v0 - mu, d1 = v1 - mu, d2 = v2 - mu, d3 = v3 - mu;
        float q = d0 * d0 + d1 * d1 + d2 * d2 + d3 * d3;
#pragma unroll
        for (int o = 16; o > 0; o >>= 1) q += __shfl_xor_sync(0xffffffffu, q, o);
        float rs = rsqrtf(q * (1.f / 128.f) + 1e-5f);
        float4 o4 = make_float4(d0 * rs, d1 * rs, d2 * rs, d3 * rs);
        *(float4*)(out + (size_t)n * DD + tx * 4) = o4;
    }
}

// ---------------- host launcher ----------------
extern "C" void kernel_launch(void* const* d_in, const int* in_sizes, int n_in,
                              void* d_out, int out_size)
{
    const float* nf        = (const float*)d_in[0];
    const float* edge_attr = (const float*)d_in[1];
    const float* edge_sh   = (const float*)d_in[2];
    const float* W_node    = (const float*)d_in[3];
    const float* fc1 = (const float*)d_in[4];
    const float* b1  = (const float*)d_in[5];
    const float* fc2 = (const float*)d_in[6];
    const float* b2  = (const float*)d_in[7];
    const float* fc3 = (const float*)d_in[8];
    const float* b3  = (const float*)d_in[9];
    const float* W_sh = (const float*)d_in[10];
    const float* aW1 = (const float*)d_in[11];
    const float* ab1 = (const float*)d_in[12];
    const float* aW2 = (const float*)d_in[13];
    const float* ab2 = (const float*)d_in[14];
    const float* aW3 = (const float*)d_in[15];
    const float* ab3 = (const float*)d_in[16];
    const float* W_out = (const float*)d_in[17];
    const int* edge_index = (const int*)d_in[18];
    float* out = (float*)d_out;

    const int SMEM_EDGE = (TE * AS + 32 * 128 + TE * 32 + TE * 16 + 640) * 4 + (2 * TE + NH) * 4;
    const int SMEM_NODE = (128 * 128 + 8 * 128) * 4;
    cudaFuncSetAttribute(k_edge, cudaFuncAttributeMaxDynamicSharedMemorySize, SMEM_EDGE);
    cudaFuncSetAttribute(k_node, cudaFuncAttributeMaxDynamicSharedMemorySize, SMEM_NODE);

    k_init<<<2048, 256>>>();
    k_edge<<<EE / TE, 256, SMEM_EDGE>>>(nf, edge_attr, edge_sh, W_node,
                                        fc1, b1, fc2, b2, fc3, b3, W_sh,
                                        aW1, ab1, aW2, ab2, aW3, ab3, edge_index);
    k_sumexp<<<1024, 256>>>();
    k_scatter<<<4096, 256>>>(edge_index);
    k_node<<<296, 256, SMEM_NODE>>>(nf, W_out, out);
}

// round 4
// speedup vs baseline: 1.7909x; 1.7909x over previous
#include <cuda_runtime.h>

#define NN 50000
#define EE 800000
#define DD 128
#define NH 8
#define TE 64
#define AS 164   // shared activation row stride (bank = 4r+c -> conflict-free frag loads)
#define WS 136   // shared weight row stride   (bank = 8c+r -> conflict-free B-frag loads)

// ---------------- scratch (static __device__ -- no allocations allowed) ----------------
__device__ float    g_a[(size_t)EE * NH];     // 25.6 MB logits
__device__ float    g_agg[(size_t)NN * DD];   // 25.6 MB
__device__ unsigned g_maxbits[NH];
__device__ float    g_sum[NH];

__device__ __forceinline__ float siluf(float x) { return x / (1.f + __expf(-x)); }
__device__ __forceinline__ unsigned encf(float x) {
    unsigned u = __float_as_uint(x);
    return (u & 0x80000000u) ? ~u : (u | 0x80000000u);
}
__device__ __forceinline__ float decf(unsigned u) {
    return __uint_as_float((u & 0x80000000u) ? (u ^ 0x80000000u) : ~u);
}
__device__ __forceinline__ unsigned f2tf(float x) {
    unsigned u;
    asm("cvt.rna.tf32.f32 %0, %1;" : "=r"(u) : "f"(x));
    return u;
}
__device__ __forceinline__ void mma8(float (&d)[4], const unsigned (&a)[4],
                                     unsigned b0, unsigned b1) {
    asm volatile(
        "mma.sync.aligned.m16n8k8.row.col.f32.tf32.tf32.f32 "
        "{%0,%1,%2,%3}, {%4,%5,%6,%7}, {%8,%9}, {%0,%1,%2,%3};\n"
        : "+f"(d[0]), "+f"(d[1]), "+f"(d[2]), "+f"(d[3])
        : "r"(a[0]), "r"(a[1]), "r"(a[2]), "r"(a[3]), "r"(b0), "r"(b1));
}

// ---------------- tf32 warp-tiled GEMM: C[64 x 128] = sA[64 x K] @ W[K x 128] ----------
// 256 threads = 8 warps. Warp w: rows (w&3)*16..+15, cols (w>>2)*64..+63 (8 n-tiles).
// acc[nt][4] per thread per mma C-fragment. W streamed gmem->shared in K-chunks of 32,
// converted to tf32 at staging. A converted to tf32 at fragment load.
template<int K, bool CLEAR>
__device__ __forceinline__ void mma_gemm(const float* __restrict__ W,
        const float* sA, int lda, float (&acc)[8][4], unsigned* sW, int tid)
{
    const int lane = tid & 31;
    const int wid  = tid >> 5;
    const int r = lane >> 2, c = lane & 3;
    const int mr0 = (wid & 3) * 16, nc0 = (wid >> 2) * 64;
    if (CLEAR) {
#pragma unroll
        for (int i = 0; i < 8; i++)
#pragma unroll
            for (int j = 0; j < 4; j++) acc[i][j] = 0.f;
    }
    constexpr int CH = (K < 32) ? K : 32;
    for (int kc = 0; kc < K; kc += CH) {
        __syncthreads();
        for (int idx = tid; idx < CH * 32; idx += 256) {
            int rr = idx >> 5, cc = (idx & 31) << 2;
            const float4 w4 = *(const float4*)(W + (size_t)(kc + rr) * DD + cc);
            unsigned* p = sW + rr * WS + cc;
            p[0] = f2tf(w4.x); p[1] = f2tf(w4.y); p[2] = f2tf(w4.z); p[3] = f2tf(w4.w);
        }
        __syncthreads();
#pragma unroll
        for (int k0 = 0; k0 < CH; k0 += 8) {
            unsigned a[4];
            const float* ap = sA + kc + k0 + c;
            a[0] = f2tf(ap[(mr0 + r) * lda]);
            a[1] = f2tf(ap[(mr0 + r + 8) * lda]);
            a[2] = f2tf(ap[(mr0 + r) * lda + 4]);
            a[3] = f2tf(ap[(mr0 + r + 8) * lda + 4]);
#pragma unroll
            for (int nt = 0; nt < 8; nt++) {
                unsigned b0 = sW[(k0 + c) * WS + nc0 + nt * 8 + r];
                unsigned b1 = sW[(k0 + c + 4) * WS + nc0 + nt * 8 + r];
                mma8(acc[nt], a, b0, b1);
            }
        }
    }
}

// bias + silu on C-fragments, store to s_A (fp32)
__device__ __forceinline__ void mma_epi_silu(const float (&acc)[8][4], const float* sb,
                                             float* s_A, int tid)
{
    const int lane = tid & 31, wid = tid >> 5;
    const int r = lane >> 2, c = lane & 3;
    const int mr0 = (wid & 3) * 16, nc0 = (wid >> 2) * 64;
#pragma unroll
    for (int nt = 0; nt < 8; nt++) {
        int col = nc0 + nt * 8 + 2 * c;
        float b0 = sb[col], b1 = sb[col + 1];
        float2 v0 = make_float2(siluf(acc[nt][0] + b0), siluf(acc[nt][1] + b1));
        float2 v1 = make_float2(siluf(acc[nt][2] + b0), siluf(acc[nt][3] + b1));
        *(float2*)(s_A + (mr0 + r) * AS + col)     = v0;
        *(float2*)(s_A + (mr0 + r + 8) * AS + col) = v1;
    }
}

// ---------------- K0: init scratch ----------------
__global__ void k_init()
{
    int i = blockIdx.x * blockDim.x + threadIdx.x;
    int stride = gridDim.x * blockDim.x;
    for (int j = i; j < NN * DD; j += stride) g_agg[j] = 0.f;
    if (i < NH) { g_maxbits[i] = 0u; g_sum[i] = 0.f; }
}

// ---------------- K1: attention logits per 64-edge tile ----------------
__global__ void __launch_bounds__(256, 2)
k_att(const float* __restrict__ nf, const float* __restrict__ edge_attr,
      const float* __restrict__ aW1, const float* __restrict__ ab1,
      const float* __restrict__ aW2, const float* __restrict__ ab2,
      const float* __restrict__ aW3, const float* __restrict__ ab3,
      const int* __restrict__ edge_index)
{
    extern __shared__ float smem[];
    float*    s_A    = smem;                    // TE*AS = 10496 f
    unsigned* s_W    = (unsigned*)(s_A + TE * AS); // 32*WS = 4352 words
    float*    s_bias = (float*)(s_W + 32 * WS); // 256 f
    int*      s_src  = (int*)(s_bias + 256);    // TE
    int*      s_dst  = s_src + TE;              // TE
    unsigned* s_maxb = (unsigned*)(s_dst + TE); // NH

    const int tid = threadIdx.x, lane = tid & 31, wid = tid >> 5;
    const int e0 = blockIdx.x * TE;

    if (tid < TE) {
        s_src[tid] = edge_index[e0 + tid];
        s_dst[tid] = edge_index[EE + e0 + tid];
    }
    if (tid < NH) s_maxb[tid] = 0u;
    if (tid < 128) {
        s_bias[tid]       = ab1[tid];
        s_bias[128 + tid] = ab2[tid];
    }
    // edge_attr -> s_A cols [128,160)
    for (int idx = tid; idx < TE * 8; idx += 256) {
        int rr = idx >> 3, cc = (idx & 7) << 2;
        *(float4*)(s_A + rr * AS + 128 + cc) =
            *(const float4*)(edge_attr + (size_t)(e0 + rr) * 32 + cc);
    }
    __syncthreads();
    // x_src[:64] -> cols [0,64), x_dst[:64] -> cols [64,128)  (warp-private rows)
#pragma unroll
    for (int i = 0; i < 8; i++) {
        int rr = wid * 8 + i;
        int s = s_src[rr], d = s_dst[rr];
        *(float2*)(s_A + rr * AS + lane * 2)      = *(const float2*)(nf + (size_t)s * DD + lane * 2);
        *(float2*)(s_A + rr * AS + 64 + lane * 2) = *(const float2*)(nf + (size_t)d * DD + lane * 2);
    }

    float acc[8][4];
    mma_gemm<160, true>(aW1, s_A, AS, acc, s_W, tid);
    __syncthreads();
    mma_epi_silu(acc, s_bias, s_A, tid);

    mma_gemm<128, true>(aW2, s_A, AS, acc, s_W, tid);
    __syncthreads();
    mma_epi_silu(acc, s_bias + 128, s_A, tid);

    // stage aW3 [128 x 8] into sW region (fp32 view)
    float* sWf = (float*)s_W;
    *(float4*)(sWf + tid * 4) = *(const float4*)(aW3 + tid * 4);
    __syncthreads();

    if (tid < TE) {
        float av[NH];
#pragma unroll
        for (int h = 0; h < NH; h++) av[h] = ab3[h];
        for (int k = 0; k < 128; k++) {
            float x = s_A[tid * AS + k];
#pragma unroll
            for (int h = 0; h < NH; h++) av[h] += x * sWf[k * 8 + h];
        }
        float4* gp = (float4*)(g_a + (size_t)(e0 + tid) * NH);
        gp[0] = make_float4(av[0], av[1], av[2], av[3]);
        gp[1] = make_float4(av[4], av[5], av[6], av[7]);
#pragma unroll
        for (int h = 0; h < NH; h++) atomicMax(&s_maxb[h], encf(av[h]));
    }
    __syncthreads();
    if (tid < NH) atomicMax(&g_maxbits[tid], s_maxb[tid]);
}

// ---------------- K2: per-head sum of exp(a - max) ----------------
__global__ void k_sumexp()
{
    __shared__ float s_sum[NH];
    if (threadIdx.x < NH) s_sum[threadIdx.x] = 0.f;
    __syncthreads();
    float mx[NH];
#pragma unroll
    for (int h = 0; h < NH; h++) mx[h] = decf(g_maxbits[h]);
    float loc[NH];
#pragma unroll
    for (int h = 0; h < NH; h++) loc[h] = 0.f;
    for (int e = blockIdx.x * blockDim.x + threadIdx.x; e < EE; e += gridDim.x * blockDim.x) {
        const float4 a0 = *(const float4*)(g_a + (size_t)e * NH);
        const float4 a1 = *(const float4*)(g_a + (size_t)e * NH + 4);
        loc[0] += __expf(a0.x - mx[0]); loc[1] += __expf(a0.y - mx[1]);
        loc[2] += __expf(a0.z - mx[2]); loc[3] += __expf(a0.w - mx[3]);
        loc[4] += __expf(a1.x - mx[4]); loc[5] += __expf(a1.y - mx[5]);
        loc[6] += __expf(a1.z - mx[6]); loc[7] += __expf(a1.w - mx[7]);
    }
#pragma unroll
    for (int h = 0; h < NH; h++) atomicAdd(&s_sum[h], loc[h]);
    __syncthreads();
    if (threadIdx.x < NH) atomicAdd(&g_sum[threadIdx.x], s_sum[threadIdx.x]);
}

// ---------------- K3: message MLP fused with weighted scatter ----------------
__global__ void __launch_bounds__(256, 2)
k_msg(const float* __restrict__ nf, const float* __restrict__ edge_attr,
      const float* __restrict__ edge_sh,
      const float* __restrict__ W_node,
      const float* __restrict__ fc1, const float* __restrict__ b1,
      const float* __restrict__ fc2, const float* __restrict__ b2,
      const float* __restrict__ fc3, const float* __restrict__ b3,
      const float* __restrict__ W_sh,
      const int* __restrict__ edge_index)
{
    extern __shared__ float smem[];
    float*    s_A    = smem;                          // TE*AS  = 10496 f
    unsigned* s_W    = (unsigned*)(s_A + TE * AS);    // 32*WS  = 4352 w
    float*    s_ea   = (float*)(s_W + 32 * WS);       // TE*36  = 2304 f
    float*    s_sh   = s_ea + TE * 36;                // TE*20  = 1280 f
    float*    s_bias = s_sh + TE * 20;                // 3*128  = 384 f
    float*    s_wt   = s_bias + 384;                  // TE
    int*      s_src  = (int*)(s_wt + TE);             // TE
    int*      s_dst  = s_src + TE;                    // TE

    const int tid = threadIdx.x, lane = tid & 31, wid = tid >> 5;
    const int r = lane >> 2, c = lane & 3;
    const int mr0 = (wid & 3) * 16, nc0 = (wid >> 2) * 64;
    const int e0 = blockIdx.x * TE;

    if (tid < TE) {
        s_src[tid] = edge_index[e0 + tid];
        s_dst[tid] = edge_index[EE + e0 + tid];
    }
    if (tid < 128) {
        s_bias[tid]       = b1[tid];
        s_bias[128 + tid] = b2[tid];
        s_bias[256 + tid] = b3[tid];
    }
    // per-edge softmax-mean weight
    if (tid < TE) {
        int e = e0 + tid;
        float w = 0.f;
#pragma unroll
        for (int h = 0; h < NH; h++)
            w += __expf(g_a[(size_t)e * NH + h] - decf(g_maxbits[h])) / g_sum[h];
        s_wt[tid] = w * 0.125f;
    }
    for (int idx = tid; idx < TE * 8; idx += 256) {     // edge_attr [TE][32] -> stride 36
        int rr = idx >> 3, cc = (idx & 7) << 2;
        *(float4*)(s_ea + rr * 36 + cc) = *(const float4*)(edge_attr + (size_t)(e0 + rr) * 32 + cc);
    }
    for (int idx = tid; idx < TE * 4; idx += 256) {     // edge_sh [TE][16] -> stride 20
        int rr = idx >> 2, cc = (idx & 3) << 2;
        *(float4*)(s_sh + rr * 20 + cc) = *(const float4*)(edge_sh + (size_t)(e0 + rr) * 16 + cc);
    }

    float acc[8][4];
    mma_gemm<32, true>(fc1, s_ea, 36, acc, s_W, tid);
    __syncthreads();
    mma_epi_silu(acc, s_bias, s_A, tid);

    mma_gemm<128, true>(fc2, s_A, AS, acc, s_W, tid);
    __syncthreads();
    mma_epi_silu(acc, s_bias + 128, s_A, tid);

    mma_gemm<128, true>(fc3, s_A, AS, acc, s_W, tid);
    float scale[8][4];
#pragma unroll
    for (int nt = 0; nt < 8; nt++) {
        int col = nc0 + nt * 8 + 2 * c;
        scale[nt][0] = acc[nt][0] + s_bias[256 + col];
        scale[nt][1] = acc[nt][1] + s_bias[256 + col + 1];
        scale[nt][2] = acc[nt][2] + s_bias[256 + col];
        scale[nt][3] = acc[nt][3] + s_bias[256 + col + 1];
    }
    __syncthreads();

    // gather full x_src rows (warp-private)
#pragma unroll
    for (int i = 0; i < 8; i++) {
        int rr = wid * 8 + i;
        int s = s_src[rr];
        *(float4*)(s_A + rr * AS + lane * 4) = *(const float4*)(nf + (size_t)s * DD + lane * 4);
    }

    mma_gemm<128, true>(W_node, s_A, AS, acc, s_W, tid);
#pragma unroll
    for (int nt = 0; nt < 8; nt++)
#pragma unroll
        for (int j = 0; j < 4; j++) acc[nt][j] *= scale[nt][j];
    mma_gemm<16, false>(W_sh, s_sh, 20, acc, s_W, tid);   // accumulate sh projection
    __syncthreads();

    // silu + alpha weight, store to s_A
#pragma unroll
    for (int nt = 0; nt < 8; nt++) {
        int col = nc0 + nt * 8 + 2 * c;
        float w0 = s_wt[mr0 + r], w1 = s_wt[mr0 + r + 8];
        float2 v0 = make_float2(siluf(acc[nt][0]) * w0, siluf(acc[nt][1]) * w0);
        float2 v1 = make_float2(siluf(acc[nt][2]) * w1, siluf(acc[nt][3]) * w1);
        *(float2*)(s_A + (mr0 + r) * AS + col)     = v0;
        *(float2*)(s_A + (mr0 + r + 8) * AS + col) = v1;
    }
    __syncthreads();

    // coalesced scatter: warp handles 8 rows, lane covers 4 cols
#pragma unroll
    for (int i = 0; i < 8; i++) {
        int rr = wid * 8 + i;
        int d = s_dst[rr];
        const float4 m = *(const float4*)(s_A + rr * AS + lane * 4);
        float* p = g_agg + (size_t)d * DD + lane * 4;
        atomicAdd(p + 0, m.x);
        atomicAdd(p + 1, m.y);
        atomicAdd(p + 2, m.z);
        atomicAdd(p + 3, m.w);
    }
}

// ---------------- K4: out = LN(nf + agg @ W_out) ----------------
__global__ void k_node(const float* __restrict__ nf, const float* __restrict__ W_out,
                       float* __restrict__ out)
{
    extern __shared__ float smem[];
    float* sW    = smem;              // 128*128
    float* s_row = sW + 128 * 128;    // 8*128
    const int tid = threadIdx.x, tx = tid & 31, w = tid >> 5;
    for (int idx = tid; idx < 128 * 32; idx += 256) {
        int r = idx >> 5, c = (idx & 31) << 2;
        *(float4*)(sW + r * 128 + c) = *(const float4*)(W_out + (size_t)r * 128 + c);
    }
    __syncthreads();
    for (int n = blockIdx.x * 8 + w; n < NN; n += gridDim.x * 8) {
        float4 av = *(const float4*)(g_agg + (size_t)n * DD + tx * 4);
        __syncwarp();
        *(float4*)(s_row + w * 128 + tx * 4) = av;
        __syncwarp();
        float a0 = 0.f, a1 = 0.f, a2 = 0.f, a3 = 0.f;
#pragma unroll 8
        for (int k = 0; k < 128; k++) {
            float a = s_row[w * 128 + k];
            const float4 wv = *(const float4*)(sW + k * 128 + tx * 4);
            a0 += a * wv.x; a1 += a * wv.y; a2 += a * wv.z; a3 += a * wv.w;
        }
        const float4 x = *(const float4*)(nf + (size_t)n * DD + tx * 4);
        float v0 = x.x + a0, v1 = x.y + a1, v2 = x.z + a2, v3 = x.w + a3;
        float s = v0 + v1 + v2 + v3;
#pragma unroll
        for (int o = 16; o > 0; o >>= 1) s += __shfl_xor_sync(0xffffffffu, s, o);
        float mu = s * (1.f / 128.f);
        float d0 = v0 - mu, d1 = v1 - mu, d2 = v2 - mu, d3 = v3 - mu;
        float q = d0 * d0 + d1 * d1 + d2 * d2 + d3 * d3;
#pragma unroll
        for (int o = 16; o > 0; o >>= 1) q += __shfl_xor_sync(0xffffffffu, q, o);
        float rs = rsqrtf(q * (1.f / 128.f) + 1e-5f);
        float4 o4 = make_float4(d0 * rs, d1 * rs, d2 * rs, d3 * rs);
        *(float4*)(out + (size_t)n * DD + tx * 4) = o4;
    }
}

// ---------------- host launcher ----------------
extern "C" void kernel_launch(void* const* d_in, const int* in_sizes, int n_in,
                              void* d_out, int out_size)
{
    const float* nf        = (const float*)d_in[0];
    const float* edge_attr = (const float*)d_in[1];
    const float* edge_sh   = (const float*)d_in[2];
    const float* W_node    = (const float*)d_in[3];
    const float* fc1 = (const float*)d_in[4];
    const float* b1  = (const float*)d_in[5];
    const float* fc2 = (const float*)d_in[6];
    const float* b2  = (const float*)d_in[7];
    const float* fc3 = (const float*)d_in[8];
    const float* b3  = (const float*)d_in[9];
    const float* W_sh = (const float*)d_in[10];
    const float* aW1 = (const float*)d_in[11];
    const float* ab1 = (const float*)d_in[12];
    const float* aW2 = (const float*)d_in[13];
    const float* ab2 = (const float*)d_in[14];
    const float* aW3 = (const float*)d_in[15];
    const float* ab3 = (const float*)d_in[16];
    const float* W_out = (const float*)d_in[17];
    const int* edge_index = (const int*)d_in[18];
    float* out = (float*)d_out;

    const int SMEM_ATT = (TE * AS + 32 * WS + 256 + 2 * TE + NH) * 4;
    const int SMEM_MSG = (TE * AS + 32 * WS + TE * 36 + TE * 20 + 384 + TE + 2 * TE) * 4;
    const int SMEM_NODE = (128 * 128 + 8 * 128) * 4;
    cudaFuncSetAttribute(k_att,  cudaFuncAttributeMaxDynamicSharedMemorySize, SMEM_ATT);
    cudaFuncSetAttribute(k_msg,  cudaFuncAttributeMaxDynamicSharedMemorySize, SMEM_MSG);
    cudaFuncSetAttribute(k_node, cudaFuncAttributeMaxDynamicSharedMemorySize, SMEM_NODE);

    k_init<<<2048, 256>>>();
    k_att<<<EE / TE, 256, SMEM_ATT>>>(nf, edge_attr, aW1, ab1, aW2, ab2, aW3, ab3, edge_index);
    k_sumexp<<<1024, 256>>>();
    k_msg<<<EE / TE, 256, SMEM_MSG>>>(nf, edge_attr, edge_sh, W_node,
                                      fc1, b1, fc2, b2, fc3, b3, W_sh, edge_index);
    k_node<<<296, 256, SMEM_NODE>>>(nf, W_out, out);
}

// round 5
// speedup vs baseline: 2.6018x; 1.4528x over previous
#include <cuda_runtime.h>
#include <cuda_bf16.h>

#define NN 50000
#define EE 800000
#define DD 128
#define NH 8
#define TE 64
#define SA 168   // s_A row stride in bf16 elems (336B -> LDSM slot = 5r mod 8, conflict-free)
#define WS2 136  // s_W row stride in bf16 elems (272B -> LDSM slot = r mod 8, conflict-free)
#define SSH 24   // s_sh row stride (48B -> slot = 3r mod 8)
#define XS 136   // s_xw row stride

// ---------------- scratch (static __device__ -- no allocations allowed) ----------------
__device__ float    g_a[(size_t)EE * NH];     // 25.6 MB logits
__device__ float    g_agg[(size_t)NN * DD];   // 25.6 MB
__device__ unsigned g_maxbits[NH];
__device__ float    g_sum[NH];

__device__ __forceinline__ float siluf(float x) { return x / (1.f + __expf(-x)); }
__device__ __forceinline__ unsigned encf(float x) {
    unsigned u = __float_as_uint(x);
    return (u & 0x80000000u) ? ~u : (u | 0x80000000u);
}
__device__ __forceinline__ float decf(unsigned u) {
    return __uint_as_float((u & 0x80000000u) ? (u ^ 0x80000000u) : ~u);
}

__device__ __forceinline__ void ldsm4(unsigned (&r)[4], unsigned addr) {
    asm volatile("ldmatrix.sync.aligned.m8n8.x4.shared.b16 {%0,%1,%2,%3}, [%4];"
                 : "=r"(r[0]), "=r"(r[1]), "=r"(r[2]), "=r"(r[3]) : "r"(addr));
}
__device__ __forceinline__ void ldsm4t(unsigned* r, unsigned addr) {
    asm volatile("ldmatrix.sync.aligned.m8n8.x4.trans.shared.b16 {%0,%1,%2,%3}, [%4];"
                 : "=r"(r[0]), "=r"(r[1]), "=r"(r[2]), "=r"(r[3]) : "r"(addr));
}
__device__ __forceinline__ void mma16(float (&d)[4], const unsigned (&a)[4],
                                      unsigned b0, unsigned b1) {
    asm volatile(
        "mma.sync.aligned.m16n8k16.row.col.f32.bf16.bf16.f32 "
        "{%0,%1,%2,%3}, {%4,%5,%6,%7}, {%8,%9}, {%0,%1,%2,%3};\n"
        : "+f"(d[0]), "+f"(d[1]), "+f"(d[2]), "+f"(d[3])
        : "r"(a[0]), "r"(a[1]), "r"(a[2]), "r"(a[3]), "r"(b0), "r"(b1));
}

// ---------------- bf16 warp-tiled GEMM: C[64 x 128] = sA[64 x K] @ W[K x 128] ----------
// 256 threads = 8 warps. Warp w: rows (w&3)*16..+15, cols (w>>2)*64..+63 (8 n8-tiles).
// W (fp32 gmem) staged -> bf16 shared in K-chunks of <=32. A read via ldmatrix.x4,
// B via ldmatrix.x4.trans. No trailing sync (callers sync before touching sA/sW).
template<int K, bool CLEAR>
__device__ __forceinline__ void bgemm(const float* __restrict__ W,
        const __nv_bfloat16* sA, int lda, float (&acc)[8][4],
        __nv_bfloat16* sW, int tid)
{
    const int lane = tid & 31, wid = tid >> 5;
    const int mr0 = (wid & 3) * 16, nc0 = (wid >> 2) * 64;
    const int lrow = lane & 15;
    const int lcol8 = (lane >> 1) & 8;    // 0 for lanes<16, 8 for lanes>=16
    if (CLEAR) {
#pragma unroll
        for (int i = 0; i < 8; i++)
#pragma unroll
            for (int j = 0; j < 4; j++) acc[i][j] = 0.f;
    }
    constexpr int CH = (K < 32) ? K : 32;
    for (int kc = 0; kc < K; kc += CH) {
        __syncthreads();
        for (int idx = tid; idx < CH * 32; idx += 256) {
            int rr = idx >> 5, cc = (idx & 31) << 2;
            const float4 w4 = *(const float4*)(W + (size_t)(kc + rr) * DD + cc);
            *(__nv_bfloat162*)(sW + rr * WS2 + cc)     = __floats2bfloat162_rn(w4.x, w4.y);
            *(__nv_bfloat162*)(sW + rr * WS2 + cc + 2) = __floats2bfloat162_rn(w4.z, w4.w);
        }
        __syncthreads();
#pragma unroll
        for (int k0 = 0; k0 < CH; k0 += 16) {
            unsigned a[4];
            ldsm4(a, (unsigned)__cvta_generic_to_shared(
                         sA + (mr0 + lrow) * lda + kc + k0 + lcol8));
            unsigned b[16];
#pragma unroll
            for (int np = 0; np < 4; np++)
                ldsm4t(b + np * 4, (unsigned)__cvta_generic_to_shared(
                           sW + (k0 + lrow) * WS2 + nc0 + np * 16 + lcol8));
#pragma unroll
            for (int nt = 0; nt < 8; nt++)
                mma16(acc[nt], a, b[(nt >> 1) * 4 + (nt & 1) * 2],
                                  b[(nt >> 1) * 4 + (nt & 1) * 2 + 1]);
        }
    }
}

// bias + silu on C-fragments, store bf16 to s_A (each (row,col) slot owned by one thread)
__device__ __forceinline__ void epi_silu(const float (&acc)[8][4], const float* sb,
                                         __nv_bfloat16* s_A, int tid)
{
    const int lane = tid & 31, wid = tid >> 5;
    const int r = lane >> 2, c = lane & 3;
    const int mr0 = (wid & 3) * 16, nc0 = (wid >> 2) * 64;
#pragma unroll
    for (int nt = 0; nt < 8; nt++) {
        int col = nc0 + nt * 8 + 2 * c;
        float b0 = sb[col], b1 = sb[col + 1];
        *(__nv_bfloat162*)(s_A + (mr0 + r) * SA + col) =
            __floats2bfloat162_rn(siluf(acc[nt][0] + b0), siluf(acc[nt][1] + b1));
        *(__nv_bfloat162*)(s_A + (mr0 + r + 8) * SA + col) =
            __floats2bfloat162_rn(siluf(acc[nt][2] + b0), siluf(acc[nt][3] + b1));
    }
}

// ---------------- K0: init scratch ----------------
__global__ void k_init()
{
    int i = blockIdx.x * blockDim.x + threadIdx.x;
    int stride = gridDim.x * blockDim.x;
    for (int j = i; j < NN * DD; j += stride) g_agg[j] = 0.f;
    if (i < NH) { g_maxbits[i] = 0u; g_sum[i] = 0.f; }
}

// ---------------- K1: attention logits per 64-edge tile ----------------
__global__ void __launch_bounds__(256, 3)
k_att(const float* __restrict__ nf, const float* __restrict__ edge_attr,
      const float* __restrict__ aW1, const float* __restrict__ ab1,
      const float* __restrict__ aW2, const float* __restrict__ ab2,
      const float* __restrict__ aW3, const float* __restrict__ ab3,
      const int* __restrict__ edge_index)
{
    extern __shared__ char smem[];
    __nv_bfloat16* s_A  = (__nv_bfloat16*)smem;                 // 64*168*2 = 21504 B
    __nv_bfloat16* s_W  = (__nv_bfloat16*)(smem + 21504);       // 32*136*2 = 8704 B
    float*    s_bias = (float*)(smem + 21504 + 8704);           // 256 f
    int*      s_src  = (int*)(s_bias + 256);                    // TE
    int*      s_dst  = s_src + TE;                              // TE
    unsigned* s_maxb = (unsigned*)(s_dst + TE);                 // NH

    const int tid = threadIdx.x, lane = tid & 31, wid = tid >> 5;
    const int e0 = blockIdx.x * TE;

    if (tid < TE) {
        s_src[tid] = edge_index[e0 + tid];
        s_dst[tid] = edge_index[EE + e0 + tid];
    }
    if (tid < NH) s_maxb[tid] = 0u;
    if (tid < 128) {
        s_bias[tid]       = ab1[tid];
        s_bias[128 + tid] = ab2[tid];
    }
    // edge_attr -> s_A cols [128,160)
    for (int idx = tid; idx < TE * 8; idx += 256) {
        int rr = idx >> 3, cc = (idx & 7) << 2;
        const float4 v = *(const float4*)(edge_attr + (size_t)(e0 + rr) * 32 + cc);
        *(__nv_bfloat162*)(s_A + rr * SA + 128 + cc)     = __floats2bfloat162_rn(v.x, v.y);
        *(__nv_bfloat162*)(s_A + rr * SA + 128 + cc + 2) = __floats2bfloat162_rn(v.z, v.w);
    }
    __syncthreads();
    // x_src[:64] -> cols [0,64), x_dst[:64] -> cols [64,128)  (warp-private rows)
#pragma unroll
    for (int i = 0; i < 8; i++) {
        int rr = wid * 8 + i;
        int s = s_src[rr], d = s_dst[rr];
        const float2 vs = *(const float2*)(nf + (size_t)s * DD + lane * 2);
        const float2 vd = *(const float2*)(nf + (size_t)d * DD + lane * 2);
        *(__nv_bfloat162*)(s_A + rr * SA + lane * 2)      = __floats2bfloat162_rn(vs.x, vs.y);
        *(__nv_bfloat162*)(s_A + rr * SA + 64 + lane * 2) = __floats2bfloat162_rn(vd.x, vd.y);
    }

    float acc[8][4];
    bgemm<160, true>(aW1, s_A, SA, acc, s_W, tid);
    __syncthreads();
    epi_silu(acc, s_bias, s_A, tid);

    bgemm<128, true>(aW2, s_A, SA, acc, s_W, tid);
    __syncthreads();
    epi_silu(acc, s_bias + 128, s_A, tid);

    // stage aW3 [128 x 8] as fp32 into s_W region
    float* sWf = (float*)s_W;
    *(float4*)(sWf + tid * 4) = *(const float4*)(aW3 + tid * 4);
    __syncthreads();

    if (tid < TE) {
        float av[NH];
#pragma unroll
        for (int h = 0; h < NH; h++) av[h] = ab3[h];
        for (int k = 0; k < 128; k++) {
            float x = __bfloat162float(s_A[tid * SA + k]);
#pragma unroll
            for (int h = 0; h < NH; h++) av[h] += x * sWf[k * 8 + h];
        }
        float4* gp = (float4*)(g_a + (size_t)(e0 + tid) * NH);
        gp[0] = make_float4(av[0], av[1], av[2], av[3]);
        gp[1] = make_float4(av[4], av[5], av[6], av[7]);
#pragma unroll
        for (int h = 0; h < NH; h++) atomicMax(&s_maxb[h], encf(av[h]));
    }
    __syncthreads();
    if (tid < NH) atomicMax(&g_maxbits[tid], s_maxb[tid]);
}

// ---------------- K2: per-head sum of exp(a - max) ----------------
__global__ void k_sumexp()
{
    __shared__ float s_sum[NH];
    if (threadIdx.x < NH) s_sum[threadIdx.x] = 0.f;
    __syncthreads();
    float mx[NH];
#pragma unroll
    for (int h = 0; h < NH; h++) mx[h] = decf(g_maxbits[h]);
    float loc[NH];
#pragma unroll
    for (int h = 0; h < NH; h++) loc[h] = 0.f;
    for (int e = blockIdx.x * blockDim.x + threadIdx.x; e < EE; e += gridDim.x * blockDim.x) {
        const float4 a0 = *(const float4*)(g_a + (size_t)e * NH);
        const float4 a1 = *(const float4*)(g_a + (size_t)e * NH + 4);
        loc[0] += __expf(a0.x - mx[0]); loc[1] += __expf(a0.y - mx[1]);
        loc[2] += __expf(a0.z - mx[2]); loc[3] += __expf(a0.w - mx[3]);
        loc[4] += __expf(a1.x - mx[4]); loc[5] += __expf(a1.y - mx[5]);
        loc[6] += __expf(a1.z - mx[6]); loc[7] += __expf(a1.w - mx[7]);
    }
#pragma unroll
    for (int h = 0; h < NH; h++) atomicAdd(&s_sum[h], loc[h]);
    __syncthreads();
    if (threadIdx.x < NH) atomicAdd(&g_sum[threadIdx.x], s_sum[threadIdx.x]);
}

// ---------------- K3: message MLP fused with weighted scatter ----------------
__global__ void __launch_bounds__(256, 3)
k_msg(const float* __restrict__ nf, const float* __restrict__ edge_attr,
      const float* __restrict__ edge_sh,
      const float* __restrict__ W_node,
      const float* __restrict__ fc1, const float* __restrict__ b1,
      const float* __restrict__ fc2, const float* __restrict__ b2,
      const float* __restrict__ fc3, const float* __restrict__ b3,
      const float* __restrict__ W_sh,
      const int* __restrict__ edge_index)
{
    extern __shared__ char smem[];
    __nv_bfloat16* s_A  = (__nv_bfloat16*)smem;                   // 21504 B
    __nv_bfloat16* s_W  = (__nv_bfloat16*)(smem + 21504);         // 8704 B
    __nv_bfloat16* s_xw = (__nv_bfloat16*)(smem + 30208);         // 64*136*2 = 17408 B
    __nv_bfloat16* s_sh = (__nv_bfloat16*)(smem + 47616);         // 64*24*2  = 3072 B
    float* s_bias = (float*)(smem + 50688);                       // 384 f
    float* s_wt   = s_bias + 384;                                 // TE
    int*   s_src  = (int*)(s_wt + TE);                            // TE
    int*   s_dst  = s_src + TE;                                   // TE

    const int tid = threadIdx.x, lane = tid & 31, wid = tid >> 5;
    const int r = lane >> 2, c = lane & 3;
    const int mr0 = (wid & 3) * 16, nc0 = (wid >> 2) * 64;
    const int e0 = blockIdx.x * TE;

    if (tid < TE) {
        s_src[tid] = edge_index[e0 + tid];
        s_dst[tid] = edge_index[EE + e0 + tid];
    }
    if (tid < 128) {
        s_bias[tid]       = b1[tid];
        s_bias[128 + tid] = b2[tid];
        s_bias[256 + tid] = b3[tid];
    }
    if (tid < TE) {     // per-edge softmax-mean weight
        int e = e0 + tid;
        float w = 0.f;
#pragma unroll
        for (int h = 0; h < NH; h++)
            w += __expf(g_a[(size_t)e * NH + h] - decf(g_maxbits[h])) / g_sum[h];
        s_wt[tid] = w * 0.125f;
    }
    for (int idx = tid; idx < TE * 4; idx += 256) {     // edge_sh [TE][16]
        int rr = idx >> 2, cc = (idx & 3) << 2;
        const float4 v = *(const float4*)(edge_sh + (size_t)(e0 + rr) * 16 + cc);
        *(__nv_bfloat162*)(s_sh + rr * SSH + cc)     = __floats2bfloat162_rn(v.x, v.y);
        *(__nv_bfloat162*)(s_sh + rr * SSH + cc + 2) = __floats2bfloat162_rn(v.z, v.w);
    }
    __syncthreads();
    // full x_src rows (warp-private) -> s_A cols [0,128)
#pragma unroll
    for (int i = 0; i < 8; i++) {
        int rr = wid * 8 + i;
        const float4 v = *(const float4*)(nf + (size_t)s_src[rr] * DD + lane * 4);
        *(__nv_bfloat162*)(s_A + rr * SA + lane * 4)     = __floats2bfloat162_rn(v.x, v.y);
        *(__nv_bfloat162*)(s_A + rr * SA + lane * 4 + 2) = __floats2bfloat162_rn(v.z, v.w);
    }

    float acc[8][4];
    // 1) xw = x_src @ W_node -> stash bf16 into s_xw (frag-owned slots, no sync needed)
    bgemm<128, true>(W_node, s_A, SA, acc, s_W, tid);
#pragma unroll
    for (int nt = 0; nt < 8; nt++) {
        int col = nc0 + nt * 8 + 2 * c;
        *(__nv_bfloat162*)(s_xw + (mr0 + r) * XS + col) =
            __floats2bfloat162_rn(acc[nt][0], acc[nt][1]);
        *(__nv_bfloat162*)(s_xw + (mr0 + r + 8) * XS + col) =
            __floats2bfloat162_rn(acc[nt][2], acc[nt][3]);
    }
    __syncthreads();

    // 2) edge_attr -> s_A cols [0,32)
    for (int idx = tid; idx < TE * 8; idx += 256) {
        int rr = idx >> 3, cc = (idx & 7) << 2;
        const float4 v = *(const float4*)(edge_attr + (size_t)(e0 + rr) * 32 + cc);
        *(__nv_bfloat162*)(s_A + rr * SA + cc)     = __floats2bfloat162_rn(v.x, v.y);
        *(__nv_bfloat162*)(s_A + rr * SA + cc + 2) = __floats2bfloat162_rn(v.z, v.w);
    }

    // 3) radial MLP
    bgemm<32, true>(fc1, s_A, SA, acc, s_W, tid);
    __syncthreads();
    epi_silu(acc, s_bias, s_A, tid);

    bgemm<128, true>(fc2, s_A, SA, acc, s_W, tid);
    __syncthreads();
    epi_silu(acc, s_bias + 128, s_A, tid);

    bgemm<128, true>(fc3, s_A, SA, acc, s_W, tid);
    __syncthreads();
    // 4) scale = fc3 + b3 -> stash bf16 into s_A (frag-owned slots)
#pragma unroll
    for (int nt = 0; nt < 8; nt++) {
        int col = nc0 + nt * 8 + 2 * c;
        float b0 = s_bias[256 + col], b1v = s_bias[256 + col + 1];
        *(__nv_bfloat162*)(s_A + (mr0 + r) * SA + col) =
            __floats2bfloat162_rn(acc[nt][0] + b0, acc[nt][1] + b1v);
        *(__nv_bfloat162*)(s_A + (mr0 + r + 8) * SA + col) =
            __floats2bfloat162_rn(acc[nt][2] + b0, acc[nt][3] + b1v);
    }

    // 5) shp = edge_sh @ W_sh
    bgemm<16, true>(W_sh, s_sh, SSH, acc, s_W, tid);

    // 6) msg = silu(xw * scale + shp) * wt -> s_xw (own slots)
#pragma unroll
    for (int nt = 0; nt < 8; nt++) {
        int col = nc0 + nt * 8 + 2 * c;
        float w0 = s_wt[mr0 + r], w1 = s_wt[mr0 + r + 8];
        float2 sc0 = __bfloat1622float2(*(__nv_bfloat162*)(s_A + (mr0 + r) * SA + col));
        float2 sc1 = __bfloat1622float2(*(__nv_bfloat162*)(s_A + (mr0 + r + 8) * SA + col));
        float2 xw0 = __bfloat1622float2(*(__nv_bfloat162*)(s_xw + (mr0 + r) * XS + col));
        float2 xw1 = __bfloat1622float2(*(__nv_bfloat162*)(s_xw + (mr0 + r + 8) * XS + col));
        *(__nv_bfloat162*)(s_xw + (mr0 + r) * XS + col) = __floats2bfloat162_rn(
            siluf(xw0.x * sc0.x + acc[nt][0]) * w0, siluf(xw0.y * sc0.y + acc[nt][1]) * w0);
        *(__nv_bfloat162*)(s_xw + (mr0 + r + 8) * XS + col) = __floats2bfloat162_rn(
            siluf(xw1.x * sc1.x + acc[nt][2]) * w1, siluf(xw1.y * sc1.y + acc[nt][3]) * w1);
    }
    __syncthreads();

    // 7) coalesced scatter: warp handles 8 rows, lane covers 4 cols
#pragma unroll
    for (int i = 0; i < 8; i++) {
        int rr = wid * 8 + i;
        int d = s_dst[rr];
        __nv_bfloat162 p0 = *(__nv_bfloat162*)(s_xw + rr * XS + lane * 4);
        __nv_bfloat162 p1 = *(__nv_bfloat162*)(s_xw + rr * XS + lane * 4 + 2);
        float2 f0 = __bfloat1622float2(p0), f1 = __bfloat1622float2(p1);
        float* p = g_agg + (size_t)d * DD + lane * 4;
        atomicAdd(p + 0, f0.x);
        atomicAdd(p + 1, f0.y);
        atomicAdd(p + 2, f1.x);
        atomicAdd(p + 3, f1.y);
    }
}

// ---------------- K4: out = LN(nf + agg @ W_out) ----------------
__global__ void k_node(const float* __restrict__ nf, const float* __restrict__ W_out,
                       float* __restrict__ out)
{
    extern __shared__ float smemf[];
    float* sW    = smemf;             // 128*128
    float* s_row = sW + 128 * 128;    // 8*128
    const int tid = threadIdx.x, tx = tid & 31, w = tid >> 5;
    for (int idx = tid; idx < 128 * 32; idx += 256) {
        int rr = idx >> 5, cc = (idx & 31) << 2;
        *(float4*)(sW + rr * 128 + cc) = *(const float4*)(W_out + (size_t)rr * 128 + cc);
    }
    __syncthreads();
    for (int n = blockIdx.x * 8 + w; n < NN; n += gridDim.x * 8) {
        float4 av = *(const float4*)(g_agg + (size_t)n * DD + tx * 4);
        __syncwarp();
        *(float4*)(s_row + w * 128 + tx * 4) = av;
        __syncwarp();
        float a0 = 0.f, a1 = 0.f, a2 = 0.f, a3 = 0.f;
#pragma unroll 8
        for (int k = 0; k < 128; k++) {
            float a = s_row[w * 128 + k];
            const float4 wv = *(const float4*)(sW + k * 128 + tx * 4);
            a0 += a * wv.x; a1 += a * wv.y; a2 += a * wv.z; a3 += a * wv.w;
        }
        const float4 x = *(const float4*)(nf + (size_t)n * DD + tx * 4);
        float v0 = x.x + a0, v1 = x.y + a1, v2 = x.z + a2, v3 = x.w + a3;
        float s = v0 + v1 + v2 + v3;
#pragma unroll
        for (int o = 16; o > 0; o >>= 1) s += __shfl_xor_sync(0xffffffffu, s, o);
        float mu = s * (1.f / 128.f);
        float d0 = v0 - mu, d1 = v1 - mu, d2 = v2 - mu, d3 = v3 - mu;
        float q = d0 * d0 + d1 * d1 + d2 * d2 + d3 * d3;
#pragma unroll
        for (int o = 16; o > 0; o >>= 1) q += __shfl_xor_sync(0xffffffffu, q, o);
        float rs = rsqrtf(q * (1.f / 128.f) + 1e-5f);
        float4 o4 = make_float4(d0 * rs, d1 * rs, d2 * rs, d3 * rs);
        *(float4*)(out + (size_t)n * DD + tx * 4) = o4;
    }
}

// ---------------- host launcher ----------------
extern "C" void kernel_launch(void* const* d_in, const int* in_sizes, int n_in,
                              void* d_out, int out_size)
{
    const float* nf        = (const float*)d_in[0];
    const float* edge_attr = (const float*)d_in[1];
    const float* edge_sh   = (const float*)d_in[2];
    const float* W_node    = (const float*)d_in[3];
    const float* fc1 = (const float*)d_in[4];
    const float* b1  = (const float*)d_in[5];
    const float* fc2 = (const float*)d_in[6];
    const float* b2  = (const float*)d_in[7];
    const float* fc3 = (const float*)d_in[8];
    const float* b3  = (const float*)d_in[9];
    const float* W_sh = (const float*)d_in[10];
    const float* aW1 = (const float*)d_in[11];
    const float* ab1 = (const float*)d_in[12];
    const float* aW2 = (const float*)d_in[13];
    const float* ab2 = (const float*)d_in[14];
    const float* aW3 = (const float*)d_in[15];
    const float* ab3 = (const float*)d_in[16];
    const float* W_out = (const float*)d_in[17];
    const int* edge_index = (const int*)d_in[18];
    float* out = (float*)d_out;

    const int SMEM_ATT  = 21504 + 8704 + 256 * 4 + (2 * TE + NH) * 4;
    const int SMEM_MSG  = 50688 + (384 + TE + 2 * TE) * 4;
    const int SMEM_NODE = (128 * 128 + 8 * 128) * 4;
    cudaFuncSetAttribute(k_att,  cudaFuncAttributeMaxDynamicSharedMemorySize, SMEM_ATT);
    cudaFuncSetAttribute(k_msg,  cudaFuncAttributeMaxDynamicSharedMemorySize, SMEM_MSG);
    cudaFuncSetAttribute(k_node, cudaFuncAttributeMaxDynamicSharedMemorySize, SMEM_NODE);

    k_init<<<2048, 256>>>();
    k_att<<<EE / TE, 256, SMEM_ATT>>>(nf, edge_attr, aW1, ab1, aW2, ab2, aW3, ab3, edge_index);
    k_sumexp<<<1024, 256>>>();
    k_msg<<<EE / TE, 256, SMEM_MSG>>>(nf, edge_attr, edge_sh, W_node,
                                      fc1, b1, fc2, b2, fc3, b3, W_sh, edge_index);
    k_node<<<296, 256, SMEM_NODE>>>(nf, W_out, out);
}